// round 7
// baseline (speedup 1.0000x reference)
#include <cuda_runtime.h>
#include <math.h>

#define H 1024
#define V 50257
#define L 12
#define NB 296                 // 2 CTAs/SM * 148 SMs, all co-resident (wave 1)
#define NT 640                 // 20 warps/block -> 40 warps/SM
#define NWALL (NB * 20)        // 5920 global warps

#define V4 12564               // full float4's in V (scalar tail = elem 50256)
#define SLICE_W 43             // 296*43 >= 12565

// ---------------- scratch ----------------
__device__ __align__(16) float g_hhp[2048];   // Whh@h0 partials (2/row)
__device__ __align__(16) float g_xp[2048];    // comb partials (2/row)
__device__ __align__(16) float g_ihp[2048];   // Wih@x partials (2/row)
__device__ __align__(16) float g_logits[V];
__device__ float g_sm[NB];
__device__ float g_ss[NB];

__device__ unsigned g_bar_arrive = 0;
__device__ volatile unsigned g_bar_gen = 0;

__device__ __forceinline__ void grid_barrier()
{
    __syncthreads();
    if (threadIdx.x == 0) {
        __threadfence();
        unsigned gen = g_bar_gen;
        unsigned t = atomicAdd(&g_bar_arrive, 1u);
        if (t == NB - 1) {
            g_bar_arrive = 0;
            __threadfence();
            g_bar_gen = gen + 1;
        } else {
            while (g_bar_gen == gen) { }
            __threadfence();
        }
    }
    __syncthreads();
}

__device__ __forceinline__ float warp_sum(float v)
{
    #pragma unroll
    for (int o = 16; o; o >>= 1) v += __shfl_xor_sync(0xffffffffu, v, o);
    return v;
}
__device__ __forceinline__ float warp_max(float v)
{
    #pragma unroll
    for (int o = 16; o; o >>= 1) v = fmaxf(v, __shfl_xor_sync(0xffffffffu, v, o));
    return v;
}
__device__ __forceinline__ void prefetch_row(const float* rowp, int lane)
{
    asm volatile("prefetch.global.L2 [%0];" :: "l"(rowp + lane * 32));
}

__global__ __launch_bounds__(NT, 2) void fused(
    const int*   __restrict__ tok,
    const float* __restrict__ hidden,
    const float* __restrict__ enc,
    const float* __restrict__ emb,
    const float* __restrict__ attn_W,
    const float* __restrict__ attn_b,
    const float* __restrict__ comb_W,
    const float* __restrict__ comb_b,
    const float* __restrict__ Wih,
    const float* __restrict__ Whh,
    const float* __restrict__ bih,
    const float* __restrict__ bhh,
    const float* __restrict__ out_W,
    const float* __restrict__ out_b,
    float* __restrict__ out_logp,
    float* __restrict__ out_h,
    float* __restrict__ out_attnw)
{
    const int tid  = threadIdx.x;
    const int bid  = blockIdx.x;
    const int lane = tid & 31;
    const int wid  = tid >> 5;               // 0..19
    const int gw   = bid * 20 + wid;         // 0..5919

    __shared__ float red[20];
    __shared__ float red2[20];
    __shared__ float s_alog[L];
    __shared__ float s_logit[20][9];
    __shared__ __align__(16) float sE[H];     // embedded -> x -> h_new
    __shared__ __align__(16) float sHid[H];
    __shared__ __align__(16) float sAtt[H];
    __shared__ float sh_c;

    const int token = tok[0];
    const float* __restrict__ erow = emb + (size_t)token * H;

    // ================= P1: attention (redundant) + comb/Whh partials ==============
    for (int i = tid; i < H; i += NT) { sE[i] = erow[i]; sHid[i] = hidden[i]; }
    __syncthreads();

    if (wid < L) {
        const float4* __restrict__ wr = (const float4*)attn_W + wid * 512;
        const float4* e4 = (const float4*)sE;
        const float4* h4 = (const float4*)sHid;
        float s = 0.f;
        #pragma unroll
        for (int k = 0; k < 8; k++) {
            float4 wv = wr[k * 32 + lane];
            float4 xv = e4[k * 32 + lane];
            s = fmaf(wv.x, xv.x, fmaf(wv.y, xv.y, fmaf(wv.z, xv.z, fmaf(wv.w, xv.w, s))));
        }
        #pragma unroll
        for (int k = 0; k < 8; k++) {
            float4 wv = wr[256 + k * 32 + lane];
            float4 xv = h4[k * 32 + lane];
            s = fmaf(wv.x, xv.x, fmaf(wv.y, xv.y, fmaf(wv.z, xv.z, fmaf(wv.w, xv.w, s))));
        }
        s = warp_sum(s);
        if (lane == 0) s_alog[wid] = s + attn_b[wid];
    }
    __syncthreads();

    float aw[L];
    {
        float mm = -INFINITY;
        #pragma unroll
        for (int j = 0; j < L; j++) { aw[j] = s_alog[j]; mm = fmaxf(mm, aw[j]); }
        float sum = 0.f;
        #pragma unroll
        for (int j = 0; j < L; j++) { aw[j] = expf(aw[j] - mm); sum += aw[j]; }
        float inv = 1.f / sum;
        #pragma unroll
        for (int j = 0; j < L; j++) aw[j] *= inv;
    }
    if (bid == 0 && tid < L) out_attnw[tid] = aw[tid];

    for (int i = tid; i < H; i += NT) {
        float a = 0.f;
        #pragma unroll
        for (int j = 0; j < L; j++) a = fmaf(aw[j], enc[j * H + i], a);
        sAtt[i] = a;
    }
    __syncthreads();

    if (gw < 2048) {
        // comb partial: row = gw>>1, 1024-elem half q
        const int row = gw >> 1, q = gw & 1;
        const float4* __restrict__ wr = (const float4*)comb_W + (size_t)row * 512 + q * 256;
        const float4* vv = q ? (const float4*)sAtt : (const float4*)sE;
        float s = 0.f;
        #pragma unroll
        for (int k = 0; k < 8; k++) {
            float4 wv = wr[k * 32 + lane];
            float4 xv = vv[k * 32 + lane];
            s = fmaf(wv.x, xv.x, fmaf(wv.y, xv.y, fmaf(wv.z, xv.z, fmaf(wv.w, xv.w, s))));
        }
        s = warp_sum(s);
        if (lane == 0) g_xp[gw] = s;
    } else if (gw < 4096) {
        // Whh partial: lw = gw-2048, 512-elem segment q
        const int lw = gw - 2048, row = lw >> 1, q = lw & 1;
        const float4* __restrict__ wr = (const float4*)Whh + (size_t)row * 256 + q * 128;
        const float4* vh = (const float4*)sHid + q * 128;
        float s = 0.f;
        #pragma unroll
        for (int k = 0; k < 4; k++) {
            float4 wv = wr[k * 32 + lane];
            float4 xv = vh[k * 32 + lane];
            s = fmaf(wv.x, xv.x, fmaf(wv.y, xv.y, fmaf(wv.z, xv.z, fmaf(wv.w, xv.w, s))));
        }
        s = warp_sum(s);
        if (lane == 0) g_hhp[lw] = s;
    } else {
        prefetch_row(out_W + (size_t)gw * H, lane);       // rows 4096..5919
    }
    grid_barrier();

    // ================= P2: x combine + Wih partials (gw < 2048) ===================
    if (gw - (size_t)bid * 20 < 20 && bid * 20 < 2048) { } // (keep structure simple)
    if (bid * 20 < 2048) {
        // this block hosts at least one working warp -> stage x
        for (int i = tid; i < H; i += NT) {
            float2 xp = ((const float2*)g_xp)[i];
            sE[i] = fmaxf(xp.x + xp.y + comb_b[i], 0.f);
        }
        __syncthreads();
    }
    if (gw < 2048) {
        const int row = gw >> 1, q = gw & 1;
        const float4* __restrict__ wr = (const float4*)Wih + (size_t)row * 256 + q * 128;
        const float4* vx = (const float4*)sE + q * 128;
        float s = 0.f;
        #pragma unroll
        for (int k = 0; k < 4; k++) {
            float4 wv = wr[k * 32 + lane];
            float4 xv = vx[k * 32 + lane];
            s = fmaf(wv.x, xv.x, fmaf(wv.y, xv.y, fmaf(wv.z, xv.z, fmaf(wv.w, xv.w, s))));
        }
        s = warp_sum(s);
        if (lane == 0) g_ihp[gw] = s;
    } else if (gw < 4096) {
        prefetch_row(out_W + (size_t)(gw - 2048) * H, lane);  // rows 0..2047
    } else {
        prefetch_row(out_W + (size_t)(gw - 4096 + 2048) * H, lane); // rows 2048..3871
    }
    grid_barrier();

    // ================= P3: h combine (redundant) + logits GEMV + LSE ==============
    for (int i = tid; i < H; i += NT) {
        float2 ih = ((const float2*)g_ihp)[i];
        float2 hh = ((const float2*)g_hhp)[i];
        float h = tanhf(ih.x + ih.y + hh.x + hh.y + bih[i] + bhh[i]);
        sE[i] = h;
        if (bid == 0) out_h[i] = h;
    }
    __syncthreads();
    {
        const float4* h4 = (const float4*)sE;
        int t = 0;
        for (int row = gw; row < V; row += NWALL) {
            const float4* __restrict__ wr = (const float4*)out_W + (size_t)row * 256 + lane;
            float4 w[8];
            #pragma unroll
            for (int k = 0; k < 8; k++) w[k] = wr[k * 32];
            float acc = 0.f;
            #pragma unroll
            for (int k = 0; k < 8; k++) {
                float4 hv = h4[k * 32 + lane];
                acc = fmaf(w[k].x, hv.x, fmaf(w[k].y, hv.y, fmaf(w[k].z, hv.z, fmaf(w[k].w, hv.w, acc))));
            }
            acc = warp_sum(acc);
            float l = acc + out_b[row];
            if (lane == 0) { g_logits[row] = l; s_logit[wid][t] = l; }
            t++;
        }
        __syncwarp();
        float v = (lane < t) ? s_logit[wid][lane] : -INFINITY;
        float wm = warp_max(v);
        float e  = (lane < t) ? expf(v - wm) : 0.f;
        float ws = warp_sum(e);
        if (lane == 0) { red[wid] = wm; red2[wid] = ws; }
        __syncthreads();
        if (wid == 0) {
            float bm = (lane < 20) ? red[lane] : -INFINITY;
            float bs = (lane < 20) ? red2[lane] : 0.f;
            #pragma unroll
            for (int o = 16; o; o >>= 1) {
                float om = __shfl_xor_sync(0xffffffffu, bm, o);
                float os = __shfl_xor_sync(0xffffffffu, bs, o);
                float nm = fmaxf(bm, om);
                bs = bs * expf(bm - nm) + os * expf(om - nm);
                bm = nm;
            }
            if (lane == 0) { g_sm[bid] = bm; g_ss[bid] = bs; }
        }
    }
    grid_barrier();

    // ================= P4: redundant merge of 296 (m,s) + write logp ==============
    if (wid == 0) {
        float bm = -INFINITY, bs = 0.f;
        for (int i = lane; i < NB; i += 32) {
            float pm = g_sm[i], ps = g_ss[i];
            float nm = fmaxf(bm, pm);
            bs = bs * expf(bm - nm) + ps * expf(pm - nm);
            bm = nm;
        }
        #pragma unroll
        for (int o = 16; o; o >>= 1) {
            float om = __shfl_xor_sync(0xffffffffu, bm, o);
            float os = __shfl_xor_sync(0xffffffffu, bs, o);
            float nm = fmaxf(bm, om);
            bs = bs * expf(bm - nm) + os * expf(om - nm);
            bm = nm;
        }
        if (lane == 0) sh_c = bm + logf(bs);
    }
    __syncthreads();
    const float c = sh_c;
    if (tid < SLICE_W) {
        int i4 = bid * SLICE_W + tid;
        if (i4 < V4) {
            float4 v = ((const float4*)g_logits)[i4];
            v.x -= c; v.y -= c; v.z -= c; v.w -= c;
            ((float4*)out_logp)[i4] = v;
        } else if (i4 == V4) {
            out_logp[V - 1] = g_logits[V - 1] - c;
        }
    }
}

// ---------------- launcher ----------------------------------------------------
extern "C" void kernel_launch(void* const* d_in, const int* in_sizes, int n_in,
                              void* d_out, int out_size)
{
    const int*   tok    = (const int*)  d_in[0];
    const float* hidden = (const float*)d_in[1];
    const float* enc    = (const float*)d_in[2];
    const float* emb    = (const float*)d_in[3];
    const float* attn_W = (const float*)d_in[4];
    const float* attn_b = (const float*)d_in[5];
    const float* comb_W = (const float*)d_in[6];
    const float* comb_b = (const float*)d_in[7];
    const float* Wih    = (const float*)d_in[8];
    const float* Whh    = (const float*)d_in[9];
    const float* bih    = (const float*)d_in[10];
    const float* bhh    = (const float*)d_in[11];
    const float* out_W  = (const float*)d_in[12];
    const float* out_b  = (const float*)d_in[13];

    float* out = (float*)d_out;
    fused<<<NB, NT>>>(tok, hidden, enc, emb, attn_W, attn_b,
                      comb_W, comb_b, Wih, Whh, bih, bhh, out_W, out_b,
                      out, out + V, out + V + H);
}

// round 9
// speedup vs baseline: 1.1515x; 1.1515x over previous
#include <cuda_runtime.h>
#include <math.h>

#define H 1024
#define V 50257
#define L 12
#define NB 148                 // K1 persistent blocks
#define NT 1024

#define ND1 6283               // K2 blocks: ceil(V/8)
#define V4 12564               // full float4's in V (scalar tail = elem 50256)
#define NEG_BIG (-1e30f)       // finite sentinel: expf(NEG_BIG - x) == 0, no NaN

// ---------------- scratch ----------------
__device__ __align__(16) float g_hhp[2048];   // Whh@h0 partials (2/row)
__device__ __align__(16) float g_xp[2048];    // comb partials (2/row)
__device__ __align__(16) float g_ihp[2048];   // Wih@x partials (2/row)
__device__ __align__(16) float g_hnew[H];
__device__ __align__(16) float g_logits[V];
__device__ float g_sm[ND1];
__device__ float g_ss[ND1];

__device__ unsigned g_bar_arrive = 0;
__device__ volatile unsigned g_bar_gen = 0;

__device__ __forceinline__ void grid_barrier()
{
    __syncthreads();
    if (threadIdx.x == 0) {
        __threadfence();
        unsigned gen = g_bar_gen;
        unsigned t = atomicAdd(&g_bar_arrive, 1u);
        if (t == NB - 1) {
            g_bar_arrive = 0;
            __threadfence();
            g_bar_gen = gen + 1;
        } else {
            while (g_bar_gen == gen) { }
            __threadfence();
        }
    }
    __syncthreads();
}

__device__ __forceinline__ float warp_sum(float v)
{
    #pragma unroll
    for (int o = 16; o; o >>= 1) v += __shfl_xor_sync(0xffffffffu, v, o);
    return v;
}
__device__ __forceinline__ float warp_max(float v)
{
    #pragma unroll
    for (int o = 16; o; o >>= 1) v = fmaxf(v, __shfl_xor_sync(0xffffffffu, v, o));
    return v;
}
__device__ __forceinline__ void prefetch_row(const float* rowp, int lane)
{
    asm volatile("prefetch.global.L2 [%0];" :: "l"(rowp + lane * 32));
}

// =================== K1: chain -> h_new (persistent, 2 grid barriers) =========
__global__ __launch_bounds__(NT, 1) void kChain(
    const int*   __restrict__ tok,
    const float* __restrict__ hidden,
    const float* __restrict__ enc,
    const float* __restrict__ emb,
    const float* __restrict__ attn_W,
    const float* __restrict__ attn_b,
    const float* __restrict__ comb_W,
    const float* __restrict__ comb_b,
    const float* __restrict__ Wih,
    const float* __restrict__ Whh,
    const float* __restrict__ bih,
    const float* __restrict__ bhh,
    const float* __restrict__ out_W,
    float* __restrict__ out_h,
    float* __restrict__ out_attnw)
{
    const int tid  = threadIdx.x;
    const int bid  = blockIdx.x;
    const int lane = tid & 31;
    const int wid  = tid >> 5;
    const int gw   = bid * 32 + wid;       // 0..4735

    __shared__ float s_alog[L];
    __shared__ __align__(16) float sE[H];   // embedded -> x
    __shared__ __align__(16) float sHid[H];
    __shared__ __align__(16) float sAtt[H];

    const int token = tok[0];
    const float* __restrict__ erow = emb + (size_t)token * H;

    // ---- P1: redundant attention + comb/Whh partials ----
    sE[tid]   = erow[tid];
    sHid[tid] = hidden[tid];
    __syncthreads();

    if (wid < L) {
        const float4* __restrict__ wr = (const float4*)attn_W + wid * 512;
        const float4* e4 = (const float4*)sE;
        const float4* h4 = (const float4*)sHid;
        float s = 0.f;
        #pragma unroll
        for (int k = 0; k < 8; k++) {
            float4 wv = wr[k * 32 + lane];
            float4 xv = e4[k * 32 + lane];
            s = fmaf(wv.x, xv.x, fmaf(wv.y, xv.y, fmaf(wv.z, xv.z, fmaf(wv.w, xv.w, s))));
        }
        #pragma unroll
        for (int k = 0; k < 8; k++) {
            float4 wv = wr[256 + k * 32 + lane];
            float4 xv = h4[k * 32 + lane];
            s = fmaf(wv.x, xv.x, fmaf(wv.y, xv.y, fmaf(wv.z, xv.z, fmaf(wv.w, xv.w, s))));
        }
        s = warp_sum(s);
        if (lane == 0) s_alog[wid] = s + attn_b[wid];
    }
    __syncthreads();

    float aw[L];
    {
        float mm = NEG_BIG;
        #pragma unroll
        for (int j = 0; j < L; j++) { aw[j] = s_alog[j]; mm = fmaxf(mm, aw[j]); }
        float sum = 0.f;
        #pragma unroll
        for (int j = 0; j < L; j++) { aw[j] = expf(aw[j] - mm); sum += aw[j]; }
        float inv = 1.f / sum;
        #pragma unroll
        for (int j = 0; j < L; j++) aw[j] *= inv;
    }
    if (bid == 0 && tid < L) out_attnw[tid] = aw[tid];

    {
        float a = 0.f;
        #pragma unroll
        for (int j = 0; j < L; j++) a = fmaf(aw[j], enc[j * H + tid], a);
        sAtt[tid] = a;
    }
    __syncthreads();

    if (gw < 2048) {
        const int row = gw >> 1, q = gw & 1;
        const float4* __restrict__ wr = (const float4*)comb_W + (size_t)row * 512 + q * 256;
        const float4* vv = q ? (const float4*)sAtt : (const float4*)sE;
        float s = 0.f;
        #pragma unroll
        for (int k = 0; k < 8; k++) {
            float4 wv = wr[k * 32 + lane];
            float4 xv = vv[k * 32 + lane];
            s = fmaf(wv.x, xv.x, fmaf(wv.y, xv.y, fmaf(wv.z, xv.z, fmaf(wv.w, xv.w, s))));
        }
        s = warp_sum(s);
        if (lane == 0) g_xp[gw] = s;
    } else if (gw < 4096) {
        const int lw = gw - 2048, row = lw >> 1, q = lw & 1;
        const float4* __restrict__ wr = (const float4*)Whh + (size_t)row * 256 + q * 128;
        const float4* vh = (const float4*)sHid + q * 128;
        float s = 0.f;
        #pragma unroll
        for (int k = 0; k < 4; k++) {
            float4 wv = wr[k * 32 + lane];
            float4 xv = vh[k * 32 + lane];
            s = fmaf(wv.x, xv.x, fmaf(wv.y, xv.y, fmaf(wv.z, xv.z, fmaf(wv.w, xv.w, s))));
        }
        s = warp_sum(s);
        if (lane == 0) g_hhp[lw] = s;
    } else {
        prefetch_row(out_W + (size_t)(gw - 4096) * H, lane);     // rows 0..639
    }
    grid_barrier();

    // ---- P2: x combine + Wih partials (blocks 0..63); others prefetch ----
    if (bid < 64) {
        float2 xp = ((const float2*)g_xp)[tid];
        sE[tid] = fmaxf(xp.x + xp.y + comb_b[tid], 0.f);
        __syncthreads();

        const int row = gw >> 1, q = gw & 1;
        const float4* __restrict__ wr = (const float4*)Wih + (size_t)row * 256 + q * 128;
        const float4* vx = (const float4*)sE + q * 128;
        float s = 0.f;
        #pragma unroll
        for (int k = 0; k < 4; k++) {
            float4 wv = wr[k * 32 + lane];
            float4 xv = vx[k * 32 + lane];
            s = fmaf(wv.x, xv.x, fmaf(wv.y, xv.y, fmaf(wv.z, xv.z, fmaf(wv.w, xv.w, s))));
        }
        s = warp_sum(s);
        if (lane == 0) g_ihp[gw] = s;
    } else {
        prefetch_row(out_W + (size_t)(gw - 2048 + 640) * H, lane); // rows 640..3327
    }
    grid_barrier();

    // ---- P3: h_new (block 0 only; kernel boundary publishes it) ----
    if (bid == 0) {
        float2 ih = ((const float2*)g_ihp)[tid];
        float2 hh = ((const float2*)g_hhp)[tid];
        float h = tanhf(ih.x + ih.y + hh.x + hh.y + bih[tid] + bhh[tid]);
        g_hnew[tid] = h;
        out_h[tid]  = h;
    }
}

// =================== K2: logits GEMV (R1 proven body) + block (m,s) ==========
__global__ __launch_bounds__(256) void kD1(const float* __restrict__ out_W,
                                           const float* __restrict__ out_b)
{
    __shared__ float4 s_h[256];
    __shared__ float red[8];
    s_h[threadIdx.x] = ((const float4*)g_hnew)[threadIdx.x];
    __syncthreads();

    const int wid = threadIdx.x >> 5, lane = threadIdx.x & 31;
    const int row = blockIdx.x * 8 + wid;

    float l = NEG_BIG;                       // finite sentinel (no -inf!)
    if (row < V) {
        const float4* __restrict__ w = (const float4*)(out_W + (size_t)row * H);
        float s = 0.f;
        #pragma unroll
        for (int k = 0; k < 8; k++) {
            float4 wv = w[k * 32 + lane];
            float4 hv = s_h[k * 32 + lane];
            s = fmaf(wv.x, hv.x, fmaf(wv.y, hv.y, fmaf(wv.z, hv.z, fmaf(wv.w, hv.w, s))));
        }
        s = warp_sum(s);
        l = s + out_b[row];
        if (lane == 0) g_logits[row] = l;
    }
    if (lane == 0) red[wid] = l;
    __syncthreads();
    if (wid == 0) {
        float v = (lane < 8) ? red[lane] : NEG_BIG;
        float m = warp_max(v);               // m finite (>=1 valid row per block)
        float e = (lane < 8) ? expf(v - m) : 0.f;  // expf(NEG_BIG - m) == 0
        float s = warp_sum(e);
        if (lane == 0) { g_sm[blockIdx.x] = m; g_ss[blockIdx.x] = s; }
    }
}

// =================== K3: redundant merge of 6283 (m,s) + write logp ==========
__global__ __launch_bounds__(256) void kFin(float* __restrict__ out_logp)
{
    __shared__ float rm[8], rs[8];
    __shared__ float sh_c;
    const int tid = threadIdx.x, lane = tid & 31, wid = tid >> 5;

    float bm = NEG_BIG, bs = 0.f;            // finite sentinel
    for (int i = tid; i < ND1; i += 256) {
        float pm = g_sm[i], ps = g_ss[i];
        float nm = fmaxf(bm, pm);
        bs = bs * expf(bm - nm) + ps * expf(pm - nm);
        bm = nm;
    }
    #pragma unroll
    for (int o = 16; o; o >>= 1) {
        float om = __shfl_xor_sync(0xffffffffu, bm, o);
        float os = __shfl_xor_sync(0xffffffffu, bs, o);
        float nm = fmaxf(bm, om);
        bs = bs * expf(bm - nm) + os * expf(om - nm);
        bm = nm;
    }
    if (lane == 0) { rm[wid] = bm; rs[wid] = bs; }
    __syncthreads();
    if (wid == 0) {
        float m2 = (lane < 8) ? rm[lane] : NEG_BIG;   // finite padding
        float s2 = (lane < 8) ? rs[lane] : 0.f;
        #pragma unroll
        for (int o = 16; o; o >>= 1) {
            float om = __shfl_xor_sync(0xffffffffu, m2, o);
            float os = __shfl_xor_sync(0xffffffffu, s2, o);
            float nm = fmaxf(m2, om);
            s2 = s2 * expf(m2 - nm) + os * expf(om - nm);
            m2 = nm;
        }
        if (lane == 0) sh_c = m2 + logf(s2);
    }
    __syncthreads();
    const float c = sh_c;

    const int idx = blockIdx.x * 256 + tid;          // 64 blocks * 256 = 16384
    if (idx < V4) {
        float4 v = ((const float4*)g_logits)[idx];
        v.x -= c; v.y -= c; v.z -= c; v.w -= c;
        ((float4*)out_logp)[idx] = v;
    } else if (idx == V4) {
        out_logp[V - 1] = g_logits[V - 1] - c;
    }
}

// ---------------- launcher ----------------------------------------------------
extern "C" void kernel_launch(void* const* d_in, const int* in_sizes, int n_in,
                              void* d_out, int out_size)
{
    const int*   tok    = (const int*)  d_in[0];
    const float* hidden = (const float*)d_in[1];
    const float* enc    = (const float*)d_in[2];
    const float* emb    = (const float*)d_in[3];
    const float* attn_W = (const float*)d_in[4];
    const float* attn_b = (const float*)d_in[5];
    const float* comb_W = (const float*)d_in[6];
    const float* comb_b = (const float*)d_in[7];
    const float* Wih    = (const float*)d_in[8];
    const float* Whh    = (const float*)d_in[9];
    const float* bih    = (const float*)d_in[10];
    const float* bhh    = (const float*)d_in[11];
    const float* out_W  = (const float*)d_in[12];
    const float* out_b  = (const float*)d_in[13];

    float* out = (float*)d_out;

    kChain<<<NB, NT>>>(tok, hidden, enc, emb, attn_W, attn_b,
                       comb_W, comb_b, Wih, Whh, bih, bhh, out_W,
                       out + V, out + V + H);
    kD1<<<ND1, 256>>>(out_W, out_b);
    kFin<<<64, 256>>>(out);
}

// round 10
// speedup vs baseline: 1.1954x; 1.0381x over previous
#include <cuda_runtime.h>
#include <math.h>

#define H 1024
#define V 50257
#define L 12
#define NB 148
#define NT 1024

#define ND1 6283               // K2 blocks: ceil(V/8)
#define V4 12564               // full float4's in V (scalar tail = elem 50256)
#define NEG_BIG (-1e30f)       // finite sentinel: expf(NEG_BIG - x) == 0, no NaN

// ---------------- scratch ----------------
__device__ __align__(16) float g_hhp[2048];   // Whh@h0 partials (2/row)
__device__ __align__(16) float g_xp[2048];    // comb partials (2/row)
__device__ __align__(16) float g_ihp[4096];   // Wih@x partials (4/row)
__device__ __align__(16) float g_hnew[H];
__device__ __align__(16) float g_logits[V];
__device__ float g_sm[ND1];
__device__ float g_ss[ND1];

__device__ unsigned g_bar_arrive = 0;
__device__ volatile unsigned g_bar_gen = 0;

__device__ __forceinline__ void grid_barrier()
{
    __syncthreads();
    if (threadIdx.x == 0) {
        __threadfence();
        unsigned gen = g_bar_gen;
        unsigned t = atomicAdd(&g_bar_arrive, 1u);
        if (t == NB - 1) {
            g_bar_arrive = 0;
            __threadfence();
            g_bar_gen = gen + 1;
        } else {
            while (g_bar_gen == gen) { }
            __threadfence();
        }
    }
    __syncthreads();
}

__device__ __forceinline__ float warp_sum(float v)
{
    #pragma unroll
    for (int o = 16; o; o >>= 1) v += __shfl_xor_sync(0xffffffffu, v, o);
    return v;
}
__device__ __forceinline__ float warp_max(float v)
{
    #pragma unroll
    for (int o = 16; o; o >>= 1) v = fmaxf(v, __shfl_xor_sync(0xffffffffu, v, o));
    return v;
}

// =================== K1: chain -> h_new (persistent, 2 grid barriers) =========
__global__ __launch_bounds__(NT, 1) void kChain(
    const int*   __restrict__ tok,
    const float* __restrict__ hidden,
    const float* __restrict__ enc,
    const float* __restrict__ emb,
    const float* __restrict__ attn_W,
    const float* __restrict__ attn_b,
    const float* __restrict__ comb_W,
    const float* __restrict__ comb_b,
    const float* __restrict__ Wih,
    const float* __restrict__ Whh,
    const float* __restrict__ bih,
    const float* __restrict__ bhh,
    float* __restrict__ out_h,
    float* __restrict__ out_attnw)
{
    const int tid  = threadIdx.x;
    const int bid  = blockIdx.x;
    const int lane = tid & 31;
    const int wid  = tid >> 5;

    __shared__ float s_alog[L];
    __shared__ __align__(16) float sE[H];   // embedded -> x
    __shared__ __align__(16) float sHid[H];
    __shared__ __align__(16) float sAtt[H];

    const int token = tok[0];
    const float* __restrict__ erow = emb + (size_t)token * H;

    // ---- P1: redundant attention; interleaved comb/Whh partials (128 blocks) ----
    sE[tid]   = erow[tid];
    sHid[tid] = hidden[tid];
    __syncthreads();

    if (wid < L) {
        const float4* __restrict__ wr = (const float4*)attn_W + wid * 512;
        const float4* e4 = (const float4*)sE;
        const float4* h4 = (const float4*)sHid;
        float s = 0.f;
        #pragma unroll
        for (int k = 0; k < 8; k++) {
            float4 wv = wr[k * 32 + lane];
            float4 xv = e4[k * 32 + lane];
            s = fmaf(wv.x, xv.x, fmaf(wv.y, xv.y, fmaf(wv.z, xv.z, fmaf(wv.w, xv.w, s))));
        }
        #pragma unroll
        for (int k = 0; k < 8; k++) {
            float4 wv = wr[256 + k * 32 + lane];
            float4 xv = h4[k * 32 + lane];
            s = fmaf(wv.x, xv.x, fmaf(wv.y, xv.y, fmaf(wv.z, xv.z, fmaf(wv.w, xv.w, s))));
        }
        s = warp_sum(s);
        if (lane == 0) s_alog[wid] = s + attn_b[wid];
    }
    __syncthreads();

    float aw[L];
    {
        float mm = NEG_BIG;
        #pragma unroll
        for (int j = 0; j < L; j++) { aw[j] = s_alog[j]; mm = fmaxf(mm, aw[j]); }
        float sum = 0.f;
        #pragma unroll
        for (int j = 0; j < L; j++) { aw[j] = expf(aw[j] - mm); sum += aw[j]; }
        float inv = 1.f / sum;
        #pragma unroll
        for (int j = 0; j < L; j++) aw[j] *= inv;
    }
    if (bid == 0 && tid < L) out_attnw[tid] = aw[tid];

    {
        float a = 0.f;
        #pragma unroll
        for (int j = 0; j < L; j++) a = fmaf(aw[j], enc[j * H + tid], a);
        sAtt[tid] = a;
    }
    __syncthreads();

    if (bid < 128) {
        if (wid < 16) {
            // comb partial: lw in 0..2047, row = lw>>1, 1024-elem half q
            const int lw = bid * 16 + wid;
            const int row = lw >> 1, q = lw & 1;
            const float4* __restrict__ wr = (const float4*)comb_W + (size_t)row * 512 + q * 256;
            const float4* vv = q ? (const float4*)sAtt : (const float4*)sE;
            float s = 0.f;
            #pragma unroll
            for (int k = 0; k < 8; k++) {
                float4 wv = wr[k * 32 + lane];
                float4 xv = vv[k * 32 + lane];
                s = fmaf(wv.x, xv.x, fmaf(wv.y, xv.y, fmaf(wv.z, xv.z, fmaf(wv.w, xv.w, s))));
            }
            s = warp_sum(s);
            if (lane == 0) g_xp[lw] = s;
        } else {
            // Whh partial: lw in 0..2047, row = lw>>1, 512-elem segment q
            const int lw = bid * 16 + (wid - 16);
            const int row = lw >> 1, q = lw & 1;
            const float4* __restrict__ wr = (const float4*)Whh + (size_t)row * 256 + q * 128;
            const float4* vh = (const float4*)sHid + q * 128;
            float s = 0.f;
            #pragma unroll
            for (int k = 0; k < 4; k++) {
                float4 wv = wr[k * 32 + lane];
                float4 xv = vh[k * 32 + lane];
                s = fmaf(wv.x, xv.x, fmaf(wv.y, xv.y, fmaf(wv.z, xv.z, fmaf(wv.w, xv.w, s))));
            }
            s = warp_sum(s);
            if (lane == 0) g_hhp[lw] = s;
        }
    }
    grid_barrier();

    // ---- P2: x combine (redundant) + Wih partials, 4-way split (128 blocks) ----
    if (bid < 128) {
        float2 xp = ((const float2*)g_xp)[tid];
        sE[tid] = fmaxf(xp.x + xp.y + comb_b[tid], 0.f);
        __syncthreads();

        const int lw = bid * 32 + wid;       // 0..4095
        const int row = lw >> 2, q = lw & 3; // 256-elem segment
        const float4* __restrict__ wr = (const float4*)Wih + (size_t)row * 256 + q * 64;
        const float4* vx = (const float4*)sE + q * 64;
        float s = 0.f;
        #pragma unroll
        for (int k = 0; k < 2; k++) {
            float4 wv = wr[k * 32 + lane];
            float4 xv = vx[k * 32 + lane];
            s = fmaf(wv.x, xv.x, fmaf(wv.y, xv.y, fmaf(wv.z, xv.z, fmaf(wv.w, xv.w, s))));
        }
        s = warp_sum(s);
        if (lane == 0) g_ihp[lw] = s;
    }
    grid_barrier();

    // ---- P3: h_new (block 0 only; kernel boundary publishes it) ----
    if (bid == 0) {
        float4 ih = ((const float4*)g_ihp)[tid];
        float2 hh = ((const float2*)g_hhp)[tid];
        float h = tanhf(ih.x + ih.y + ih.z + ih.w + hh.x + hh.y + bih[tid] + bhh[tid]);
        g_hnew[tid] = h;
        out_h[tid]  = h;
    }
}

// =================== K2: logits GEMV (R1 proven body) + block (m,s) ==========
__global__ __launch_bounds__(256) void kD1(const float* __restrict__ out_W,
                                           const float* __restrict__ out_b)
{
    __shared__ float4 s_h[256];
    __shared__ float red[8];
    s_h[threadIdx.x] = ((const float4*)g_hnew)[threadIdx.x];
    __syncthreads();

    const int wid = threadIdx.x >> 5, lane = threadIdx.x & 31;
    const int row = blockIdx.x * 8 + wid;

    float l = NEG_BIG;
    if (row < V) {
        const float4* __restrict__ w = (const float4*)(out_W + (size_t)row * H);
        float s = 0.f;
        #pragma unroll
        for (int k = 0; k < 8; k++) {
            float4 wv = w[k * 32 + lane];
            float4 hv = s_h[k * 32 + lane];
            s = fmaf(wv.x, hv.x, fmaf(wv.y, hv.y, fmaf(wv.z, hv.z, fmaf(wv.w, hv.w, s))));
        }
        s = warp_sum(s);
        l = s + out_b[row];
        if (lane == 0) g_logits[row] = l;
    }
    if (lane == 0) red[wid] = l;
    __syncthreads();
    if (wid == 0) {
        float v = (lane < 8) ? red[lane] : NEG_BIG;
        float m = warp_max(v);
        float e = (lane < 8) ? expf(v - m) : 0.f;
        float s = warp_sum(e);
        if (lane == 0) { g_sm[blockIdx.x] = m; g_ss[blockIdx.x] = s; }
    }
}

// =================== K3: redundant merge of 6283 (m,s) + write logp ==========
__global__ __launch_bounds__(256) void kFin(float* __restrict__ out_logp)
{
    __shared__ float rm[8], rs[8];
    __shared__ float sh_c;
    const int tid = threadIdx.x, lane = tid & 31, wid = tid >> 5;

    float bm = NEG_BIG, bs = 0.f;
    for (int i = tid; i < ND1; i += 256) {
        float pm = g_sm[i], ps = g_ss[i];
        float nm = fmaxf(bm, pm);
        bs = bs * expf(bm - nm) + ps * expf(pm - nm);
        bm = nm;
    }
    #pragma unroll
    for (int o = 16; o; o >>= 1) {
        float om = __shfl_xor_sync(0xffffffffu, bm, o);
        float os = __shfl_xor_sync(0xffffffffu, bs, o);
        float nm = fmaxf(bm, om);
        bs = bs * expf(bm - nm) + os * expf(om - nm);
        bm = nm;
    }
    if (lane == 0) { rm[wid] = bm; rs[wid] = bs; }
    __syncthreads();
    if (wid == 0) {
        float m2 = (lane < 8) ? rm[lane] : NEG_BIG;
        float s2 = (lane < 8) ? rs[lane] : 0.f;
        #pragma unroll
        for (int o = 16; o; o >>= 1) {
            float om = __shfl_xor_sync(0xffffffffu, m2, o);
            float os = __shfl_xor_sync(0xffffffffu, s2, o);
            float nm = fmaxf(m2, om);
            s2 = s2 * expf(m2 - nm) + os * expf(om - nm);
            m2 = nm;
        }
        if (lane == 0) sh_c = m2 + logf(s2);
    }
    __syncthreads();
    const float c = sh_c;

    const int idx = blockIdx.x * 256 + tid;          // 64 * 256 = 16384 >= 12565
    if (idx < V4) {
        float4 v = ((const float4*)g_logits)[idx];
        v.x -= c; v.y -= c; v.z -= c; v.w -= c;
        ((float4*)out_logp)[idx] = v;
    } else if (idx == V4) {
        out_logp[V - 1] = g_logits[V - 1] - c;
    }
}

// ---------------- launcher ----------------------------------------------------
extern "C" void kernel_launch(void* const* d_in, const int* in_sizes, int n_in,
                              void* d_out, int out_size)
{
    const int*   tok    = (const int*)  d_in[0];
    const float* hidden = (const float*)d_in[1];
    const float* enc    = (const float*)d_in[2];
    const float* emb    = (const float*)d_in[3];
    const float* attn_W = (const float*)d_in[4];
    const float* attn_b = (const float*)d_in[5];
    const float* comb_W = (const float*)d_in[6];
    const float* comb_b = (const float*)d_in[7];
    const float* Wih    = (const float*)d_in[8];
    const float* Whh    = (const float*)d_in[9];
    const float* bih    = (const float*)d_in[10];
    const float* bhh    = (const float*)d_in[11];
    const float* out_W  = (const float*)d_in[12];
    const float* out_b  = (const float*)d_in[13];

    float* out = (float*)d_out;

    kChain<<<NB, NT>>>(tok, hidden, enc, emb, attn_W, attn_b,
                       comb_W, comb_b, Wih, Whh, bih, bhh,
                       out + V, out + V + H);
    kD1<<<ND1, 256>>>(out_W, out_b);
    kFin<<<64, 256>>>(out);
}